// round 11
// baseline (speedup 1.0000x reference)
#include <cuda_runtime.h>

// Problem constants (fixed by setup_inputs)
#define M_PTS   1024
#define BATCH   2
#define NC      64
#define NCEN    (BATCH * NC)       // 128 centers
#define KS      13
#define NA      20
#define DOUT    64
#define KP      (KS * NA)          // 260 kernel positions
#define R2      0.16f              // RADIUS^2
// S = -log2(e) / (2*SIGMA) = -1.4426950408889634 / 0.16
#define S_CONST (-9.016844005556021f)
#define M2S     (18.033688011112042f)   // -2*S

#define Q        4                 // point-quarters per center
#define PTS_BLK  (M_PTS / Q)       // 256 points per block

#define NT1      320               // 10 warps
#define NW1      (NT1 / 32)

// Fixed-slot scratch: deterministic combine, no allocation.
__device__ float g_partial[NCEN][Q][KP];
__device__ int   g_cnt[NCEN][Q];
__device__ int   g_ticket[NCEN];   // zero-initialized; reset to 0 by combiner

__device__ __forceinline__ float ex2(float x) {
    float y;
    asm("ex2.approx.ftz.f32 %0, %1;" : "=f"(y) : "f"(x));
    return y;
}

__global__ __launch_bounds__(NT1, 2)
void kp_fused_kernel(const float* __restrict__ frag,      // (M,3)
                     const float* __restrict__ clouds,    // (B,3,NC)
                     const float* __restrict__ kernels,   // (KS,NA,3) -> [KP][3]
                     const float* __restrict__ W,         // (DOUT,KS)
                     float* __restrict__ out)             // (B,DOUT,NC,NA)
{
    __shared__ float4 s_pts[PTS_BLK];    // {rx, ry, rz, ex2(S*|r|^2)}
    __shared__ float  s_wts[KP];
    __shared__ float  s_W[DOUT * KS];
    __shared__ int    s_wcnt[NW1];
    __shared__ int    s_win;

    const int tid  = threadIdx.x;
    const int lane = tid & 31;
    const int wrp  = tid >> 5;

    const int blk    = blockIdx.x;
    const int center = blk >> 2;         // / Q
    const int q      = blk & 3;          // % Q
    const int bb     = center >> 6;      // / NC
    const int n      = center & 63;      // % NC

    // kernel position for this thread (1 thread per KP; tail threads idle)
    const bool valid = (tid < KP);
    const int  kp    = valid ? tid : 0;
    const float kx = kernels[3 * kp + 0];
    const float ky = kernels[3 * kp + 1];
    const float kz = kernels[3 * kp + 2];

    const float cx = clouds[bb * 3 * NC + 0 * NC + n];
    const float cy = clouds[bb * 3 * NC + 1 * NC + n];
    const float cz = clouds[bb * 3 * NC + 2 * NC + n];

    // Preload conv weights (only the combiner uses them; cheap, L2-resident)
    for (int idx = tid; idx < DOUT * KS; idx += NT1) s_W[idx] = W[idx];

    // ---- compaction of this block's 256-point quarter (single ballot round) ----
    const int i = q * PTS_BLK + tid;     // threads 256..319 -> pred false
    bool pred = false;
    float rx = 0.f, ry = 0.f, rz = 0.f, rn2 = 0.f;
    if (tid < PTS_BLK) {
        rx = frag[3 * i + 0] - cx;
        ry = frag[3 * i + 1] - cy;
        rz = frag[3 * i + 2] - cz;
        rn2 = fmaf(rz, rz, fmaf(ry, ry, rx * rx));
        pred = rn2 < R2;
    }
    const unsigned bal = __ballot_sync(0xffffffffu, pred);
    if (lane == 0) s_wcnt[wrp] = __popc(bal);
    __syncthreads();
    int prefix = 0, cnt = 0;
    #pragma unroll
    for (int w = 0; w < NW1; w++) {
        const int c = s_wcnt[w];
        if (w < wrp) prefix += c;
        cnt += c;
    }
    if (pred) {
        const int pos = prefix + __popc(bal & ((1u << lane) - 1u));
        s_pts[pos] = make_float4(rx, ry, rz, ex2(rn2 * S_CONST));
    }
    __syncthreads();

    if (tid == 0) g_cnt[center][q] = cnt;

    // ---- gaussian partial accumulation over the quarter-list ----
    if (valid) {
        const float ps = fmaf(kz, kz, fmaf(ky, ky, kx * kx)) * S_CONST;

        float a0 = 0.f, a1 = 0.f, a2 = 0.f, a3 = 0.f;
        int j = 0;
        for (; j + 3 < cnt; j += 4) {
            const float4 r0 = s_pts[j + 0];
            const float4 r1 = s_pts[j + 1];
            const float4 r2 = s_pts[j + 2];
            const float4 r3 = s_pts[j + 3];
            const float d0 = fmaf(r0.z, kz, fmaf(r0.y, ky, r0.x * kx));
            const float d1 = fmaf(r1.z, kz, fmaf(r1.y, ky, r1.x * kx));
            const float d2 = fmaf(r2.z, kz, fmaf(r2.y, ky, r2.x * kx));
            const float d3 = fmaf(r3.z, kz, fmaf(r3.y, ky, r3.x * kx));
            a0 = fmaf(r0.w, ex2(fmaf(d0, M2S, ps)), a0);
            a1 = fmaf(r1.w, ex2(fmaf(d1, M2S, ps)), a1);
            a2 = fmaf(r2.w, ex2(fmaf(d2, M2S, ps)), a2);
            a3 = fmaf(r3.w, ex2(fmaf(d3, M2S, ps)), a3);
        }
        for (; j < cnt; j++) {
            const float4 r0 = s_pts[j];
            const float d0 = fmaf(r0.z, kz, fmaf(r0.y, ky, r0.x * kx));
            a0 = fmaf(r0.w, ex2(fmaf(d0, M2S, ps)), a0);
        }
        g_partial[center][q][kp] = (a0 + a1) + (a2 + a3);
    }

    // ---- ticket: last quarter-block of this center does combine + conv ----
    __threadfence();
    __syncthreads();
    if (tid == 0) {
        const int old = atomicAdd(&g_ticket[center], 1);
        const int win = (old == Q - 1);
        s_win = win;
        if (win) g_ticket[center] = 0;   // reset for next graph replay
    }
    __syncthreads();
    if (!s_win) return;

    // combiner: partials from all Q quarter-blocks are visible
    // (threadfence before each block's ticket increment).
    if (valid) {
        const float s = ((g_partial[center][0][kp] + g_partial[center][1][kp]) +
                         (g_partial[center][2][kp] + g_partial[center][3][kp]));
        const int c4 = ((g_cnt[center][0] + g_cnt[center][1]) +
                        (g_cnt[center][2] + g_cnt[center][3]));
        s_wts[kp] = __fdividef(s, (float)c4 + 1.0f);
    }
    __syncthreads();

    // 1x1 SO3 conv: feats[b,o,n,a] = sum_k W[o,k] * wts[k*NA + a]
    for (int oa = tid; oa < DOUT * NA; oa += NT1) {
        const int o = oa / NA;
        const int a = oa % NA;
        float s = 0.f;
        #pragma unroll
        for (int k = 0; k < KS; k++)
            s = fmaf(s_W[o * KS + k], s_wts[k * NA + a], s);
        out[(bb * DOUT + o) * (NC * NA) + n * NA + a] = s;
    }
}

extern "C" void kernel_launch(void* const* d_in, const int* in_sizes, int n_in,
                              void* d_out, int out_size) {
    const float* frag    = (const float*)d_in[0];   // (1024,3)
    const float* clouds  = (const float*)d_in[1];   // (2,3,64)
    const float* kernels = (const float*)d_in[2];   // (13,20,3)
    const float* W       = (const float*)d_in[3];   // (64,13)
    float* out = (float*)d_out;                     // (2,64,64,20)

    kp_fused_kernel<<<NCEN * Q, NT1>>>(frag, clouds, kernels, W, out);
}

// round 14
// speedup vs baseline: 1.3988x; 1.3988x over previous
#include <cuda_runtime.h>

// Problem constants (fixed by setup_inputs)
#define M_PTS   1024
#define BATCH   2
#define NC      64
#define NCEN    (BATCH * NC)       // 128 centers
#define KS      13
#define NA      20
#define DOUT    64
#define KP      (KS * NA)          // 260 kernel positions
#define R2      0.16f              // RADIUS^2
// S = -log2(e) / (2*SIGMA) = -1.4426950408889634 / 0.16
#define S_CONST (-9.016844005556021f)
#define M2S     (18.033688011112042f)   // -2*S

#define NT      1024               // one block per center, 32 warps
#define NW      (NT / 32)
// kps with index < KP4 have 4 workers; the rest have 3 (NT = 4*KP4 + 3*(KP-KP4))
#define KP4     (NT - 3 * KP)      // 244

__device__ __forceinline__ float ex2(float x) {
    float y;
    asm("ex2.approx.ftz.f32 %0, %1;" : "=f"(y) : "f"(x));
    return y;
}

__global__ __launch_bounds__(NT, 1)
void kp_fused_kernel(const float* __restrict__ frag,      // (M,3)
                     const float* __restrict__ clouds,    // (B,3,NC)
                     const float* __restrict__ kernels,   // (KS,NA,3) -> [KP][3]
                     const float* __restrict__ W,         // (DOUT,KS)
                     float* __restrict__ out)             // (B,DOUT,NC,NA)
{
    __shared__ float4 s_pts[M_PTS];      // {rx, ry, rz, ex2(S*|r|^2)}
    __shared__ float  s_part[4][KP];     // per-(par,kp) partial sums
    __shared__ float  s_wts[KP];
    __shared__ float  s_W[DOUT * KS];
    __shared__ int    s_wcnt[NW];
    __shared__ int    s_total;           // separate word: no read/write race

    const int tid  = threadIdx.x;
    const int lane = tid & 31;
    const int wrp  = tid >> 5;

    const int center = blockIdx.x;       // b*NC + n
    const int bb     = center >> 6;      // / NC
    const int n      = center & 63;      // % NC

    // thread -> (kernel position, worker index). kps 0..KP4-1 get 4 workers,
    // kps KP4..259 get 3. Stride MUST equal the kp's worker count.
    const int kp   = tid % KP;
    const int par  = tid / KP;           // 0..3 (par==3 only for kp < KP4)
    const int npar = (kp < KP4) ? 4 : 3; // this kp's worker count / stride

    const float kx = kernels[3 * kp + 0];
    const float ky = kernels[3 * kp + 1];
    const float kz = kernels[3 * kp + 2];

    const float cx = clouds[bb * 3 * NC + 0 * NC + n];
    const float cy = clouds[bb * 3 * NC + 1 * NC + n];
    const float cz = clouds[bb * 3 * NC + 2 * NC + n];

    // Preload conv weights into shared (overlaps with phase 1)
    for (int idx = tid; idx < DOUT * KS; idx += NT) s_W[idx] = W[idx];

    // ---------------- Phase 1: one-shot in-ball compaction (1024 pts) ----------
    {
        const float rx = frag[3 * tid + 0] - cx;
        const float ry = frag[3 * tid + 1] - cy;
        const float rz = frag[3 * tid + 2] - cz;
        const float rn2 = fmaf(rz, rz, fmaf(ry, ry, rx * rx));
        const bool pred = rn2 < R2;

        const unsigned bal = __ballot_sync(0xffffffffu, pred);
        if (lane == 0) s_wcnt[wrp] = __popc(bal);
        __syncthreads();
        int prefix = 0, total = 0;
        #pragma unroll
        for (int w = 0; w < NW; w++) {
            const int c = s_wcnt[w];
            if (w < wrp) prefix += c;
            total += c;
        }
        if (pred) {
            const int pos = prefix + __popc(bal & ((1u << lane) - 1u));
            s_pts[pos] = make_float4(rx, ry, rz, ex2(rn2 * S_CONST));
        }
        s_total = total;                 // all threads write the identical value
        __syncthreads();
    }
    const int cnt = s_total;

    // ------- Phase 2: gaussian accumulation, npar workers per kernel position --
    {
        const float ps = fmaf(kz, kz, fmaf(ky, ky, kx * kx)) * S_CONST;

        float a0 = 0.f, a1 = 0.f, a2 = 0.f, a3 = 0.f;
        const int st1 = npar, st2 = 2 * npar, st3 = 3 * npar, st4 = 4 * npar;
        int j = par;
        for (; j + st3 < cnt; j += st4) {
            const float4 r0 = s_pts[j];
            const float4 r1 = s_pts[j + st1];
            const float4 r2 = s_pts[j + st2];
            const float4 r3 = s_pts[j + st3];
            const float d0 = fmaf(r0.z, kz, fmaf(r0.y, ky, r0.x * kx));
            const float d1 = fmaf(r1.z, kz, fmaf(r1.y, ky, r1.x * kx));
            const float d2 = fmaf(r2.z, kz, fmaf(r2.y, ky, r2.x * kx));
            const float d3 = fmaf(r3.z, kz, fmaf(r3.y, ky, r3.x * kx));
            a0 = fmaf(r0.w, ex2(fmaf(d0, M2S, ps)), a0);
            a1 = fmaf(r1.w, ex2(fmaf(d1, M2S, ps)), a1);
            a2 = fmaf(r2.w, ex2(fmaf(d2, M2S, ps)), a2);
            a3 = fmaf(r3.w, ex2(fmaf(d3, M2S, ps)), a3);
        }
        for (; j < cnt; j += st1) {
            const float4 r0 = s_pts[j];
            const float d0 = fmaf(r0.z, kz, fmaf(r0.y, ky, r0.x * kx));
            a0 = fmaf(r0.w, ex2(fmaf(d0, M2S, ps)), a0);
        }
        s_part[par][kp] = (a0 + a1) + (a2 + a3);
        // ghost slots: kp KP4..259 have no par-3 worker (no writer -> no race)
        if (tid < KP - KP4) s_part[3][KP4 + tid] = 0.f;
    }
    __syncthreads();

    // ---------------- combine partials (fixed order -> deterministic) ----------
    if (tid < KP) {
        const float s = ((s_part[0][tid] + s_part[1][tid]) +
                         (s_part[2][tid] + s_part[3][tid]));
        s_wts[tid] = __fdividef(s, (float)cnt + 1.0f);
    }
    __syncthreads();

    // ---------------- Phase 3: 1x1 SO3 conv + store ----------------------------
    // feats[b,o,n,a] = sum_k W[o,k] * wts[k*NA + a]
    for (int oa = tid; oa < DOUT * NA; oa += NT) {
        const int o = oa / NA;
        const int a = oa % NA;
        float s = 0.f;
        #pragma unroll
        for (int k = 0; k < KS; k++)
            s = fmaf(s_W[o * KS + k], s_wts[k * NA + a], s);
        out[(bb * DOUT + o) * (NC * NA) + n * NA + a] = s;
    }
}

extern "C" void kernel_launch(void* const* d_in, const int* in_sizes, int n_in,
                              void* d_out, int out_size) {
    const float* frag    = (const float*)d_in[0];   // (1024,3)
    const float* clouds  = (const float*)d_in[1];   // (2,3,64)
    const float* kernels = (const float*)d_in[2];   // (13,20,3)
    const float* W       = (const float*)d_in[3];   // (64,13)
    float* out = (float*)d_out;                     // (2,64,64,20)

    kp_fused_kernel<<<NCEN, NT>>>(frag, clouds, kernels, W, out);
}